// round 2
// baseline (speedup 1.0000x reference)
#include <cuda_runtime.h>
#include <math.h>

#define Hdim   192
#define K2H    384
#define Pdim   64
#define BM     128
#define BN     128
#define BKt    16
#define TPB    256
#define RADIUS 0.42f
#define BRS    0.18f
#define NEGINF -1e9f

// shared layout (floats)
#define SZ_AS  (16*132)
#define SZ_BS  (16*132)
#define SZ_LS  (128*129)
#define SZ_DS  (128*65)
#define SZ_PV  (64*192)
#define SZ_POS (192)
#define SZ_BIA (128)
#define OFF_AS  0
#define OFF_BS  (OFF_AS+SZ_AS)
#define OFF_LS  (OFF_BS+SZ_BS)
#define OFF_DS  (OFF_LS+SZ_LS)
#define OFF_PV  (OFF_DS+SZ_DS)
#define OFF_POS (OFF_PV+SZ_PV)
#define OFF_BIA (OFF_POS+SZ_POS)
#define SMEM_FLOATS (OFF_BIA+SZ_BIA)

__global__ void __launch_bounds__(TPB, 1)
taps_fused_kernel(const float* __restrict__ token,
                  const float* __restrict__ prev,
                  const float* __restrict__ Wsel,
                  const float* __restrict__ bsel,
                  const float* __restrict__ Wbr,
                  const float* __restrict__ bbr,
                  const float* __restrict__ pvals,
                  const float* __restrict__ ppos,
                  float* __restrict__ out,
                  int Btot)
{
    extern __shared__ float sm[];
    float* As   = sm + OFF_AS;   // [16][132], As[k][row]
    float* Bs   = sm + OFF_BS;   // [16][132], Bs[k][p]
    float* Ls   = sm + OFF_LS;   // [128][129] logits -> base_weights -> final weights
    float* Ds   = sm + OFF_DS;   // [128][65] distances
    float* pv   = sm + OFF_PV;   // [64*192]
    float* pos  = sm + OFF_POS;  // pos[p], pos[64+p], pos[128+p]
    float* bias = sm + OFF_BIA;  // [128]

    const int tid = threadIdx.x;
    const int r0  = blockIdx.x * BM;

    // preload patch values / positions / biases (visibility covered by later syncs)
    for (int i = tid; i < SZ_PV; i += TPB) pv[i] = pvals[i];
    for (int i = tid; i < 192; i += TPB) {
        int p = i / 3, c = i % 3;
        pos[c * 64 + p] = ppos[i];
    }
    if (tid < 128) bias[tid] = (tid < 64) ? bsel[tid] : bbr[tid - 64];

    // ---------------- GEMM1: logits[128 rows][128 p] ----------------
    float acc[8][8];
#pragma unroll
    for (int i = 0; i < 8; i++)
#pragma unroll
        for (int j = 0; j < 8; j++) acc[i][j] = 0.f;

    const int tx = tid & 15;   // p tile
    const int ty = tid >> 4;   // row tile
    const int cl = tid & 15;   // k within tile (loads)
    const int rl = tid >> 4;   // row/p base (loads)

    for (int k0 = 0; k0 < K2H; k0 += BKt) {
        __syncthreads();
        // A tile: query = concat(token, prev) -- whole 16-wide k tile is one source
        const float* qs = (k0 < Hdim) ? token : prev;
        const int kc = (k0 < Hdim) ? (k0 + cl) : (k0 + cl - Hdim);
#pragma unroll
        for (int i = 0; i < 8; i++) {
            int r = rl + i * 16;
            As[cl * 132 + r] = qs[(size_t)(r0 + r) * Hdim + kc];
        }
        // B tile: W_cat rows (0..63 = W_sel, 64..127 = W_br)
#pragma unroll
        for (int i = 0; i < 8; i++) {
            int p = rl + i * 16;
            const float* ws = (p < 64) ? (Wsel + (size_t)p * K2H)
                                       : (Wbr + (size_t)(p - 64) * K2H);
            Bs[cl * 132 + p] = ws[k0 + cl];
        }
        __syncthreads();
#pragma unroll
        for (int c = 0; c < BKt; c++) {
            float4 a0 = *(const float4*)(As + c * 132 + ty * 8);
            float4 a1 = *(const float4*)(As + c * 132 + ty * 8 + 4);
            float4 b0 = *(const float4*)(Bs + c * 132 + tx * 8);
            float4 b1 = *(const float4*)(Bs + c * 132 + tx * 8 + 4);
            float a[8] = {a0.x, a0.y, a0.z, a0.w, a1.x, a1.y, a1.z, a1.w};
            float b[8] = {b0.x, b0.y, b0.z, b0.w, b1.x, b1.y, b1.z, b1.w};
#pragma unroll
            for (int i = 0; i < 8; i++)
#pragma unroll
                for (int j = 0; j < 8; j++)
                    acc[i][j] = fmaf(a[i], b[j], acc[i][j]);
        }
    }
    __syncthreads();
    // logits (+bias) into shared
#pragma unroll
    for (int i = 0; i < 8; i++) {
        int lr = ty * 8 + i;
#pragma unroll
        for (int j = 0; j < 8; j++) {
            int p = tx * 8 + j;
            Ls[lr * 129 + p] = acc[i][j] + bias[p];
        }
    }
    __syncthreads();

    // ---------------- per-row epilogue ----------------
    if (tid < 128) {
        const int lr = tid;
        const int row = r0 + lr;
        float* Lrow = Ls + lr * 129;
        float* Drow = Ds + lr * 65;

        // softmax over sel logits
        float m = -3.4e38f;
        for (int p = 0; p < 64; p++) m = fmaxf(m, Lrow[p]);
        float s = 0.f;
        for (int p = 0; p < 64; p++) { float e = expf(Lrow[p] - m); Lrow[p] = e; s += e; }
        const float invs = 1.f / s;

        // base_weights + anchor position
        float ax = 0.f, ay = 0.f, az = 0.f;
        for (int p = 0; p < 64; p++) {
            float w = Lrow[p] * invs;
            Lrow[p] = w;
            ax = fmaf(w, pos[p], ax);
            ay = fmaf(w, pos[64 + p], ay);
            az = fmaf(w, pos[128 + p], az);
        }

        // distances + argmin (first occurrence)
        float dmin = 3.4e38f; int pmin = 0;
        for (int p = 0; p < 64; p++) {
            float dx = ax - pos[p], dy = ay - pos[64 + p], dz = az - pos[128 + p];
            float d = sqrtf(dx * dx + dy * dy + dz * dz);
            Drow[p] = d;
            if (d < dmin) { dmin = d; pmin = p; }
        }

        // local part of mixed (local count provably <= 3)
        const float inv2r2 = 1.f / (2.f * RADIUS * RADIUS);
        int nl = 0; int lp[12]; float lw[12];
        float msum = 0.f;
        for (int p = 0; p < 64; p++) {
            float d = Drow[p];
            if (d <= RADIUS || p == pmin) {
                float mix = Lrow[p] * expf(-(d * d) * inv2r2);
                if (nl < 12) { lp[nl] = p; lw[nl] = mix; nl++; }
                msum += mix;
            }
        }

        // top-6 of masked bridge logits (stable: strict > keeps lowest index)
        float bv[6]; int bi[6];
#pragma unroll
        for (int k = 0; k < 6; k++) {
            float best = -3.4e38f; int bb = 0;
            for (int p = 0; p < 64; p++) {
                bool ch = false;
#pragma unroll
                for (int j = 0; j < 6; j++)
                    if (j < k) ch |= (bi[j] == p);
                if (ch) continue;
                float d = Drow[p];
                float v = (d <= RADIUS || p == pmin) ? NEGINF : Lrow[64 + p];
                if (v > best) { best = v; bb = p; }
            }
            bv[k] = best; bi[k] = bb;
        }
        const float mb = bv[0];
        float sb[6]; float es = 0.f;
#pragma unroll
        for (int k = 0; k < 6; k++) { sb[k] = expf(bv[k] - mb); es += sb[k]; }
        const float invb = 1.f / es;
#pragma unroll
        for (int k = 0; k < 6; k++) { sb[k] = BRS * (sb[k] * invb); msum += sb[k]; }

        const float denom = fmaxf(msum, 1e-6f);

        // final weights (sparse) -> stored dense in Lrow for coalesced writeback
        for (int p = 0; p < 64; p++) Lrow[p] = 0.f;
        float lmass = 0.f, bmass = 0.f, mdist = 0.f;
        int n = 0; int plist[20]; float wl[20];
        for (int i = 0; i < nl; i++) {
            float w = lw[i] / denom;
            Lrow[lp[i]] = w;
            lmass += w;
            mdist = fmaf(w, Drow[lp[i]], mdist);
            plist[n] = lp[i]; wl[n] = w; n++;
        }
#pragma unroll
        for (int k = 0; k < 6; k++) {
            float w = sb[k] / denom;
            Lrow[bi[k]] = w;
            bmass += w;
            mdist = fmaf(w, Drow[bi[k]], mdist);
            plist[n] = bi[k]; wl[n] = w; n++;
        }

        // scalar outputs
        const size_t Bt = (size_t)Btot;
        float* o_ap = out + Bt * 256;
        o_ap[(size_t)row * 3 + 0] = ax;
        o_ap[(size_t)row * 3 + 1] = ay;
        o_ap[(size_t)row * 3 + 2] = az;
        out[Bt * 259 + row] = lmass;
        out[Bt * 260 + row] = bmass;
        out[Bt * 261 + row] = mdist;
        out[Bt * 262 + row] = RADIUS;
        out[Bt * 263 + row] = BRS;

        // patch_state = sparse weights @ patch_values
        float* ops = out + (size_t)row * Hdim;
        for (int h = 0; h < Hdim; h += 4) {
            float4 a4 = {0.f, 0.f, 0.f, 0.f};
            for (int i = 0; i < n; i++) {
                const float4 v = *(const float4*)(pv + plist[i] * Hdim + h);
                a4.x = fmaf(wl[i], v.x, a4.x);
                a4.y = fmaf(wl[i], v.y, a4.y);
                a4.z = fmaf(wl[i], v.z, a4.z);
                a4.w = fmaf(wl[i], v.w, a4.w);
            }
            *(float4*)(ops + h) = a4;
        }
    }
    __syncthreads();

    // coalesced writeback of dense weights tile
    float* ow = out + (size_t)Btot * Hdim;
    for (int i = tid; i < BM * 64; i += TPB) {
        int r = i >> 6, p = i & 63;
        ow[(size_t)(r0 + r) * 64 + p] = Ls[r * 129 + p];
    }
}

extern "C" void kernel_launch(void* const* d_in, const int* in_sizes, int n_in,
                              void* d_out, int out_size)
{
    const float* token = (const float*)d_in[0];
    const float* prev  = (const float*)d_in[1];
    const float* Wsel  = (const float*)d_in[2];
    const float* bsel  = (const float*)d_in[3];
    const float* Wbr   = (const float*)d_in[4];
    const float* bbr   = (const float*)d_in[5];
    const float* pvals = (const float*)d_in[6];
    const float* ppos  = (const float*)d_in[7];
    float* out = (float*)d_out;

    const int B = in_sizes[0] / Hdim;
    const int smem_bytes = SMEM_FLOATS * (int)sizeof(float);
    cudaFuncSetAttribute(taps_fused_kernel,
                         cudaFuncAttributeMaxDynamicSharedMemorySize, smem_bytes);
    const int grid = B / BM;   // B = 262144 -> 2048 blocks
    taps_fused_kernel<<<grid, TPB, smem_bytes>>>(token, prev, Wsel, bsel, Wbr, bbr,
                                                 pvals, ppos, out, B);
}

// round 12
// speedup vs baseline: 1.6353x; 1.6353x over previous
#include <cuda_runtime.h>
#include <math.h>
#include <cstdint>

#define TPB    512
#define BM     256
#define BK     16
#define Hdim   192
#define K2H    384
#define RADIUS 0.42f
#define BRS    0.18f
#define NEGINF -1e9f

typedef unsigned long long ull;

// ---- smem (bytes) ----
// epilogue arena
#define OFF_LSH  0            // 256*130*4 = 133120
#define OFF_PV   133120       // 64*192*4 = 49152 -> 182272
#define OFF_CNT  182272       // 256*4 -> 183296
#define OFF_PL   183296       // 256*12*4 -> 195584
#define OFF_WL   195584       // 256*12*4 -> 207872
#define OFF_POS  207872       // 192*4 -> 208640
#define OFF_BIAS 208640       // 128*4 -> 209152
#define SMEM_BYTES 209152
// GEMM overlay (inside [0, 51200), dead before Lsh is written)
#define OFF_AS   0            // 2 bufs * 16*264*4 = 2*16896
#define OFF_BS   33792        // 2 bufs * 16*136*4 = 2*8704 -> 51200
#define AS_BUF_F (16*264)     // floats per A buf
#define BS_BUF_F (16*136)

#define PACK2(dst, x, y) asm("mov.b64 %0, {%1, %2};" : "=l"(dst) : "r"(x), "r"(y))
#define FFMA2(acc, a, b) asm("fma.rn.f32x2 %0, %1, %2, %0;" : "+l"(acc) : "l"(a), "l"(b))
#define UNPK2(lo, hi, v) asm("mov.b64 {%0, %1}, %2;" : "=r"(lo), "=r"(hi) : "l"(v))

__global__ void __launch_bounds__(TPB, 1)
taps_f32x2_kernel(const float* __restrict__ token,
                  const float* __restrict__ prev,
                  const float* __restrict__ Wsel,
                  const float* __restrict__ bsel,
                  const float* __restrict__ Wbr,
                  const float* __restrict__ bbr,
                  const float* __restrict__ pvals,
                  const float* __restrict__ ppos,
                  float* __restrict__ out,
                  int Btot)
{
    extern __shared__ float sm[];
    float* As   = sm + (OFF_AS  >> 2);
    float* Bs   = sm + (OFF_BS  >> 2);
    float* Lsh  = sm + (OFF_LSH >> 2);
    float* pvS  = sm + (OFF_PV  >> 2);
    int*   cntS = (int*)(sm + (OFF_CNT >> 2));
    int*   plS  = (int*)(sm + (OFF_PL  >> 2));
    float* wlS  = sm + (OFF_WL  >> 2);
    float* posS = sm + (OFF_POS >> 2);
    float* biasS= sm + (OFF_BIAS>> 2);

    const int tid  = threadIdx.x;
    const int lane = tid & 31;
    const int w    = tid >> 5;          // warp 0..15: owns cols w*8..w*8+7
    const int r0   = blockIdx.x * BM;

    for (int i = tid; i < 192; i += TPB) { int p = i / 3, c = i % 3; posS[c * 64 + p] = ppos[i]; }
    if (tid < 128) biasS[tid] = (tid < 64) ? bsel[tid] : bbr[tid - 64];

    // staging slot assignment (fixed per thread): two A float4 slots + one B slot
    const int sA0 = tid;            // A slot 0..511
    const int sA1 = tid + 512;      // A slot 512..1023
    const int sB  = tid;            // B slot 0..511
    const int a0row = sA0 >> 2, a0f4 = sA0 & 3;
    const int a1row = sA1 >> 2, a1f4 = sA1 & 3;
    const int brow  = sB  >> 2, bf4  = sB  & 3;
    const float* wsrc = (brow < 64) ? (Wsel + (size_t)brow * K2H)
                                    : (Wbr + (size_t)(brow - 64) * K2H);

    // accumulators: 8 rows (lane + 32j) x 4 col-pairs
    ull acc[8][4];
#pragma unroll
    for (int j = 0; j < 8; j++)
#pragma unroll
        for (int p = 0; p < 4; p++) acc[j][p] = 0ull;

    float4 vA0, vA1, vB;

    // prologue: load chunk 0 and stage to buf 0
    {
        const int gk = 0;
        vA0 = *(const float4*)(token + (size_t)(r0 + a0row) * Hdim + gk + a0f4 * 4);
        vA1 = *(const float4*)(token + (size_t)(r0 + a1row) * Hdim + gk + a1f4 * 4);
        vB  = *(const float4*)(wsrc + gk + bf4 * 4);
        float* A = As;  float* Bst = Bs;
        A[(a0f4 * 4 + 0) * 264 + a0row] = vA0.x;
        A[(a0f4 * 4 + 1) * 264 + a0row] = vA0.y;
        A[(a0f4 * 4 + 2) * 264 + a0row] = vA0.z;
        A[(a0f4 * 4 + 3) * 264 + a0row] = vA0.w;
        A[(a1f4 * 4 + 0) * 264 + a1row] = vA1.x;
        A[(a1f4 * 4 + 1) * 264 + a1row] = vA1.y;
        A[(a1f4 * 4 + 2) * 264 + a1row] = vA1.z;
        A[(a1f4 * 4 + 3) * 264 + a1row] = vA1.w;
        Bst[(bf4 * 4 + 0) * 136 + brow] = vB.x;
        Bst[(bf4 * 4 + 1) * 136 + brow] = vB.y;
        Bst[(bf4 * 4 + 2) * 136 + brow] = vB.z;
        Bst[(bf4 * 4 + 3) * 136 + brow] = vB.w;
    }

    // ---- GEMM1 main loop: 24 chunks of BK=16, double-buffered ----
    for (int ch = 0; ch < 24; ch++) {
        __syncthreads();
        const bool more = (ch < 23);
        if (more) {
            const int gk = (ch + 1) * BK;
            const float* Asrc = (gk < Hdim) ? token : prev;
            const int acol = (gk < Hdim) ? gk : gk - Hdim;
            vA0 = *(const float4*)(Asrc + (size_t)(r0 + a0row) * Hdim + acol + a0f4 * 4);
            vA1 = *(const float4*)(Asrc + (size_t)(r0 + a1row) * Hdim + acol + a1f4 * 4);
            vB  = *(const float4*)(wsrc + gk + bf4 * 4);
        }

        const float* Ab = As + (ch & 1) * AS_BUF_F;
        const float* Bb = Bs + (ch & 1) * BS_BUF_F + w * 8;
#pragma unroll
        for (int k = 0; k < BK; k++) {
            const float* Ak = Ab + k * 264;
            float4 b01 = *(const float4*)(Bb + k * 136);
            float4 b23 = *(const float4*)(Bb + k * 136 + 4);
            ull bb0, bb1, bb2, bb3;
            PACK2(bb0, __float_as_uint(b01.x), __float_as_uint(b01.y));
            PACK2(bb1, __float_as_uint(b01.z), __float_as_uint(b01.w));
            PACK2(bb2, __float_as_uint(b23.x), __float_as_uint(b23.y));
            PACK2(bb3, __float_as_uint(b23.z), __float_as_uint(b23.w));
#pragma unroll
            for (int j = 0; j < 8; j++) {
                const float a = Ak[lane + 32 * j];
                ull aa;
                const uint32_t au = __float_as_uint(a);
                PACK2(aa, au, au);
                FFMA2(acc[j][0], aa, bb0);
                FFMA2(acc[j][1], aa, bb1);
                FFMA2(acc[j][2], aa, bb2);
                FFMA2(acc[j][3], aa, bb3);
            }
        }

        if (more) {
            float* A = As + ((ch + 1) & 1) * AS_BUF_F;
            float* Bst = Bs + ((ch + 1) & 1) * BS_BUF_F;
            A[(a0f4 * 4 + 0) * 264 + a0row] = vA0.x;
            A[(a0f4 * 4 + 1) * 264 + a0row] = vA0.y;
            A[(a0f4 * 4 + 2) * 264 + a0row] = vA0.z;
            A[(a0f4 * 4 + 3) * 264 + a0row] = vA0.w;
            A[(a1f4 * 4 + 0) * 264 + a1row] = vA1.x;
            A[(a1f4 * 4 + 1) * 264 + a1row] = vA1.y;
            A[(a1f4 * 4 + 2) * 264 + a1row] = vA1.z;
            A[(a1f4 * 4 + 3) * 264 + a1row] = vA1.w;
            Bst[(bf4 * 4 + 0) * 136 + brow] = vB.x;
            Bst[(bf4 * 4 + 1) * 136 + brow] = vB.y;
            Bst[(bf4 * 4 + 2) * 136 + brow] = vB.z;
            Bst[(bf4 * 4 + 3) * 136 + brow] = vB.w;
        }
    }
    __syncthreads();   // GEMM bufs dead; epilogue arena live

    // ---- stage logits (+bias) into Lsh ----
    {
        const int col = w * 8;
        float b[8];
#pragma unroll
        for (int p = 0; p < 8; p++) b[p] = biasS[col + p];
#pragma unroll
        for (int j = 0; j < 8; j++) {
            const int row = lane + 32 * j;
#pragma unroll
            for (int p = 0; p < 4; p++) {
                uint32_t lo, hi;
                UNPK2(lo, hi, acc[j][p]);
                float2 v = make_float2(__uint_as_float(lo) + b[p * 2],
                                       __uint_as_float(hi) + b[p * 2 + 1]);
                *(float2*)&Lsh[row * 130 + col + p * 2] = v;
            }
        }
    }
    for (int i = tid; i < 64 * 192; i += TPB) pvS[i] = pvals[i];
    __syncthreads();

    // ---- per-row epilogue (round-2 validated semantics) ----
    if (tid < BM) {
        const int r = tid;
        const int row = r0 + r;
        float* Lrow = Lsh + r * 130;

        // softmax over sel logits
        float m = -3.4e38f;
        for (int p = 0; p < 64; p++) m = fmaxf(m, Lrow[p]);
        float s = 0.f;
        for (int p = 0; p < 64; p++) { float e = expf(Lrow[p] - m); Lrow[p] = e; s += e; }
        const float invs = 1.f / s;

        // base_weights + anchor position
        float ax = 0.f, ay = 0.f, az = 0.f;
        for (int p = 0; p < 64; p++) {
            float wgt = Lrow[p] * invs;
            Lrow[p] = wgt;
            ax = fmaf(wgt, posS[p], ax);
            ay = fmaf(wgt, posS[64 + p], ay);
            az = fmaf(wgt, posS[128 + p], az);
        }

        // distances + argmin (first occurrence) + local mask bits
        float dmin = 3.4e38f; int pmin = 0;
        unsigned long long mask = 0ull;
        for (int p = 0; p < 64; p++) {
            float dx = ax - posS[p], dy = ay - posS[64 + p], dz = az - posS[128 + p];
            float d = sqrtf(dx * dx + dy * dy + dz * dz);
            if (d < dmin) { dmin = d; pmin = p; }
            if (d <= RADIUS) mask |= 1ull << p;
        }
        mask |= 1ull << pmin;

        // local part of mixed (recompute d with identical expression)
        const float inv2r2 = 1.f / (2.f * RADIUS * RADIUS);
        int nl = 0; int lp[12]; float lw[12], ldst[12];
        float msum = 0.f;
        for (int p = 0; p < 64; p++) {
            if ((mask >> p) & 1ull) {
                float dx = ax - posS[p], dy = ay - posS[64 + p], dz = az - posS[128 + p];
                float d = sqrtf(dx * dx + dy * dy + dz * dz);
                float mix = Lrow[p] * expf(-(d * d) * inv2r2);
                if (nl < 12) { lp[nl] = p; lw[nl] = mix; ldst[nl] = d; nl++; }
                msum += mix;
            }
        }

        // top-6 of masked bridge logits (stable iterative strict-max)
        float bv[6]; int bi[6];
#pragma unroll
        for (int kq = 0; kq < 6; kq++) {
            float best = -3.4e38f; int bb = 0;
            for (int p = 0; p < 64; p++) {
                bool ch = false;
#pragma unroll
                for (int jq = 0; jq < 6; jq++)
                    if (jq < kq) ch |= (bi[jq] == p);
                if (ch) continue;
                float v = ((mask >> p) & 1ull) ? NEGINF : Lrow[64 + p];
                if (v > best) { best = v; bb = p; }
            }
            bv[kq] = best; bi[kq] = bb;
        }
        const float mb = bv[0];
        float sb[6]; float es = 0.f;
#pragma unroll
        for (int kq = 0; kq < 6; kq++) { sb[kq] = expf(bv[kq] - mb); es += sb[kq]; }
        const float invb = 1.f / es;
#pragma unroll
        for (int kq = 0; kq < 6; kq++) { sb[kq] = BRS * (sb[kq] * invb); msum += sb[kq]; }

        const float denom = fmaxf(msum, 1e-6f);

        // final sparse weights (dense in Lrow cols 0..63 for writeback)
        for (int p = 0; p < 64; p++) Lrow[p] = 0.f;
        float lmass = 0.f, bmass = 0.f, mdist = 0.f;
        int n = 0;
        for (int i = 0; i < nl; i++) {
            float wgt = lw[i] / denom;
            Lrow[lp[i]] = wgt;
            lmass += wgt;
            mdist = fmaf(wgt, ldst[i], mdist);
            plS[r * 12 + n] = lp[i]; wlS[r * 12 + n] = wgt; n++;
        }
#pragma unroll
        for (int kq = 0; kq < 6; kq++) {
            float wgt = sb[kq] / denom;
            int p = bi[kq];
            Lrow[p] = wgt;
            bmass += wgt;
            float dx = ax - posS[p], dy = ay - posS[64 + p], dz = az - posS[128 + p];
            float d = sqrtf(dx * dx + dy * dy + dz * dz);
            mdist = fmaf(wgt, d, mdist);
            plS[r * 12 + n] = p; wlS[r * 12 + n] = wgt; n++;
        }
        cntS[r] = n;

        // scalar outputs
        const size_t Bt = (size_t)Btot;
        float* o_ap = out + Bt * 256;
        o_ap[(size_t)row * 3 + 0] = ax;
        o_ap[(size_t)row * 3 + 1] = ay;
        o_ap[(size_t)row * 3 + 2] = az;
        out[Bt * 259 + row] = lmass;
        out[Bt * 260 + row] = bmass;
        out[Bt * 261 + row] = mdist;
        out[Bt * 262 + row] = RADIUS;
        out[Bt * 263 + row] = BRS;
    }
    __syncthreads();

    // ---- GEMM2: patch_state = sparse weights @ patch_values (coalesced f4) ----
    const float4* pv4 = (const float4*)pvS;
    float4* out4 = (float4*)out;
    for (int c = tid; c < BM * 48; c += TPB) {
        const int r = c / 48, h4 = c - r * 48;
        const int n = cntS[r];
        float4 a4 = make_float4(0.f, 0.f, 0.f, 0.f);
        for (int i = 0; i < n; i++) {
            const float wgt = wlS[r * 12 + i];
            const int p = plS[r * 12 + i];
            const float4 v = pv4[p * 48 + h4];
            a4.x = fmaf(wgt, v.x, a4.x);
            a4.y = fmaf(wgt, v.y, a4.y);
            a4.z = fmaf(wgt, v.z, a4.z);
            a4.w = fmaf(wgt, v.w, a4.w);
        }
        out4[(size_t)(r0 + r) * 48 + h4] = a4;
    }

    // ---- dense weights writeback ----
    float* outw = out + (size_t)Btot * Hdim;
    for (int i = tid; i < BM * 64; i += TPB) {
        const int r = i >> 6, p = i & 63;
        outw[(size_t)(r0 + r) * 64 + p] = Lsh[r * 130 + p];
    }
}

extern "C" void kernel_launch(void* const* d_in, const int* in_sizes, int n_in,
                              void* d_out, int out_size)
{
    const float* token = (const float*)d_in[0];
    const float* prev  = (const float*)d_in[1];
    const float* Wsel  = (const float*)d_in[2];
    const float* bsel  = (const float*)d_in[3];
    const float* Wbr   = (const float*)d_in[4];
    const float* bbr   = (const float*)d_in[5];
    const float* pvals = (const float*)d_in[6];
    const float* ppos  = (const float*)d_in[7];
    float* out = (float*)d_out;

    const int B = in_sizes[0] / Hdim;
    cudaFuncSetAttribute(taps_f32x2_kernel,
                         cudaFuncAttributeMaxDynamicSharedMemorySize, SMEM_BYTES);
    taps_f32x2_kernel<<<B / BM, TPB, SMEM_BYTES>>>(token, prev, Wsel, bsel, Wbr, bbr,
                                                   pvals, ppos, out, B);
}

// round 14
// speedup vs baseline: 1.7577x; 1.0748x over previous
#include <cuda_runtime.h>
#include <math.h>
#include <cstdint>

#define TPB    256
#define BM     128
#define BK     32
#define NCH    12
#define Hdim   192
#define K2H    384
#define RADIUS 0.42f
#define BRS    0.18f
#define NEGINF -1e9f

typedef unsigned long long ull;

// ---- smem (bytes) ----
// GEMM overlay: A [k][row] stride 138 floats, B [k][p] stride 132 floats
#define AS_STR  138
#define BS_STR  132
#define AS_BUF  (BK*AS_STR)      // 4416 floats
#define BS_BUF  (BK*BS_STR)      // 4224 floats
#define OFF_AS  0                // 2*4416*4 = 35328
#define OFF_BS  35328            // 2*4224*4 = 33792 -> 69120
// epilogue arena (all written AFTER GEMM completes; overlays AS/BS)
#define OFF_LSH  0               // 128*130*4 = 66560
#define OFF_CNT  66560           // 512 -> 67072
#define OFF_PL   67072           // 128*12*4 -> 73216
#define OFF_WL   73216           // 128*12*4 -> 79360
// live across whole kernel (beyond GEMM region end 69120)
#define OFF_POS  79360           // 192*4 -> 80128
#define OFF_BIAS 80128           // 128*4 -> 80640
#define SMEM_BYTES 80640

#define PACK2(dst, x, y) asm("mov.b64 %0, {%1, %2};" : "=l"(dst) : "r"(x), "r"(y))
#define FFMA2(acc, a, b) asm("fma.rn.f32x2 %0, %1, %2, %0;" : "+l"(acc) : "l"(a), "l"(b))
#define UNPK2(lo, hi, v) asm("mov.b64 {%0, %1}, %2;" : "=r"(lo), "=r"(hi) : "l"(v))

__global__ void __launch_bounds__(TPB, 2)
taps_f32x2_kernel(const float* __restrict__ token,
                  const float* __restrict__ prev,
                  const float* __restrict__ Wsel,
                  const float* __restrict__ bsel,
                  const float* __restrict__ Wbr,
                  const float* __restrict__ bbr,
                  const float* __restrict__ pvals,
                  const float* __restrict__ ppos,
                  float* __restrict__ out,
                  int Btot)
{
    extern __shared__ float sm[];
    float* As   = sm + (OFF_AS  >> 2);
    float* Bs   = sm + (OFF_BS  >> 2);
    float* Lsh  = sm + (OFF_LSH >> 2);
    int*   cntS = (int*)(sm + (OFF_CNT >> 2));
    int*   plS  = (int*)(sm + (OFF_PL  >> 2));
    float* wlS  = sm + (OFF_WL  >> 2);
    float* posS = sm + (OFF_POS >> 2);
    float* biasS= sm + (OFF_BIAS>> 2);

    const int tid  = threadIdx.x;
    const int lane = tid & 31;
    const int w    = tid >> 5;            // warp 0..7: cols [w*16, w*16+16)
    const int r0   = blockIdx.x * BM;

    for (int i = tid; i < 192; i += TPB) { int p = i / 3, c = i % 3; posS[c * 64 + p] = ppos[i]; }
    if (tid < 128) biasS[tid] = (tid < 64) ? bsel[tid] : bbr[tid - 64];

    // ---- staging geometry (fixed per thread) ----
    const int f4    = tid & 7;            // float4 index along k within chunk
    const int rbase = tid >> 3;           // 0..31
    int aoff[4];
    const float* wp[4];
#pragma unroll
    for (int i = 0; i < 4; i++) {
        const int row = i * 32 + rbase;   // A row / B patch row
        aoff[i] = (r0 + row) * Hdim + f4 * 4;
        wp[i] = ((row < 64) ? (Wsel + (size_t)row * K2H)
                            : (Wbr + (size_t)(row - 64) * K2H)) + f4 * 4;
    }

    // ---- compute geometry ----
    const int g0 = lane & 7;                       // row-pair base
    const int c0 = w * 16 + ((lane >> 3) << 2);    // 4 output cols

    ull acc[8][4];
#pragma unroll
    for (int j = 0; j < 8; j++)
#pragma unroll
        for (int q = 0; q < 4; q++) acc[j][q] = 0ull;

    float4 vA[4], vB[4];

    // prologue: load chunk 0, store into buf 0
#pragma unroll
    for (int i = 0; i < 4; i++) {
        vA[i] = *(const float4*)(token + aoff[i]);
        vB[i] = *(const float4*)(wp[i]);
    }
    {
        float* A = As; float* Bst = Bs;
#pragma unroll
        for (int i = 0; i < 4; i++) {
            const int row = i * 32 + rbase;
            A[(f4 * 4 + 0) * AS_STR + row] = vA[i].x;
            A[(f4 * 4 + 1) * AS_STR + row] = vA[i].y;
            A[(f4 * 4 + 2) * AS_STR + row] = vA[i].z;
            A[(f4 * 4 + 3) * AS_STR + row] = vA[i].w;
            Bst[(f4 * 4 + 0) * BS_STR + row] = vB[i].x;
            Bst[(f4 * 4 + 1) * BS_STR + row] = vB[i].y;
            Bst[(f4 * 4 + 2) * BS_STR + row] = vB[i].z;
            Bst[(f4 * 4 + 3) * BS_STR + row] = vB[i].w;
        }
    }

    // ---- GEMM1: 12 chunks of BK=32, double-buffered ----
    for (int ch = 0; ch < NCH; ch++) {
        __syncthreads();
        const bool more = (ch < NCH - 1);
        if (more) {
            const int gk = (ch + 1) * BK;
            const float* Asrc = (gk < Hdim) ? token : prev;
            const int acol = (gk < Hdim) ? gk : gk - Hdim;
#pragma unroll
            for (int i = 0; i < 4; i++) {
                vA[i] = *(const float4*)(Asrc + aoff[i] + acol);
                vB[i] = *(const float4*)(wp[i] + gk);
            }
        }

        const ull*   A64 = (const ull*)(As + (ch & 1) * AS_BUF);
        const float* Bb  = Bs + (ch & 1) * BS_BUF + c0;
#pragma unroll
        for (int k = 0; k < BK; k++) {
            const ull* Ak = A64 + k * (AS_STR / 2);
            float4 b4 = *(const float4*)(Bb + k * BS_STR);
            ull bb0, bb1, bb2, bb3;
            const uint32_t u0 = __float_as_uint(b4.x), u1 = __float_as_uint(b4.y);
            const uint32_t u2 = __float_as_uint(b4.z), u3 = __float_as_uint(b4.w);
            PACK2(bb0, u0, u0);
            PACK2(bb1, u1, u1);
            PACK2(bb2, u2, u2);
            PACK2(bb3, u3, u3);
#pragma unroll
            for (int j = 0; j < 8; j++) {
                const ull aa = Ak[g0 + 8 * j];   // rows {2(g0+8j), 2(g0+8j)+1}
                FFMA2(acc[j][0], aa, bb0);
                FFMA2(acc[j][1], aa, bb1);
                FFMA2(acc[j][2], aa, bb2);
                FFMA2(acc[j][3], aa, bb3);
            }
        }

        if (more) {
            float* A   = As + ((ch + 1) & 1) * AS_BUF;
            float* Bst = Bs + ((ch + 1) & 1) * BS_BUF;
#pragma unroll
            for (int i = 0; i < 4; i++) {
                const int row = i * 32 + rbase;
                A[(f4 * 4 + 0) * AS_STR + row] = vA[i].x;
                A[(f4 * 4 + 1) * AS_STR + row] = vA[i].y;
                A[(f4 * 4 + 2) * AS_STR + row] = vA[i].z;
                A[(f4 * 4 + 3) * AS_STR + row] = vA[i].w;
                Bst[(f4 * 4 + 0) * BS_STR + row] = vB[i].x;
                Bst[(f4 * 4 + 1) * BS_STR + row] = vB[i].y;
                Bst[(f4 * 4 + 2) * BS_STR + row] = vB[i].z;
                Bst[(f4 * 4 + 3) * BS_STR + row] = vB[i].w;
            }
        }
    }
    __syncthreads();   // GEMM bufs dead; epilogue arena live

    // ---- stage logits (+bias) into Lsh ----
    {
        float b[4];
#pragma unroll
        for (int q = 0; q < 4; q++) b[q] = biasS[c0 + q];
#pragma unroll
        for (int j = 0; j < 8; j++) {
            const int row0 = 2 * (g0 + 8 * j);
#pragma unroll
            for (int q = 0; q < 4; q++) {
                uint32_t lo, hi;
                UNPK2(lo, hi, acc[j][q]);
                Lsh[row0 * 130 + c0 + q]       = __uint_as_float(lo) + b[q];
                Lsh[(row0 + 1) * 130 + c0 + q] = __uint_as_float(hi) + b[q];
            }
        }
    }
    __syncthreads();

    // ---- per-row epilogue (round-2/12 validated semantics) ----
    if (tid < BM) {
        const int r = tid;
        const int row = r0 + r;
        float* Lrow = Lsh + r * 130;

        // softmax over sel logits
        float m = -3.4e38f;
        for (int p = 0; p < 64; p++) m = fmaxf(m, Lrow[p]);
        float s = 0.f;
        for (int p = 0; p < 64; p++) { float e = expf(Lrow[p] - m); Lrow[p] = e; s += e; }
        const float invs = 1.f / s;

        // base_weights + anchor position
        float ax = 0.f, ay = 0.f, az = 0.f;
        for (int p = 0; p < 64; p++) {
            float wgt = Lrow[p] * invs;
            Lrow[p] = wgt;
            ax = fmaf(wgt, posS[p], ax);
            ay = fmaf(wgt, posS[64 + p], ay);
            az = fmaf(wgt, posS[128 + p], az);
        }

        // distances + argmin (first occurrence) + local mask bits
        float dmin = 3.4e38f; int pmin = 0;
        unsigned long long mask = 0ull;
        for (int p = 0; p < 64; p++) {
            float dx = ax - posS[p], dy = ay - posS[64 + p], dz = az - posS[128 + p];
            float d = sqrtf(dx * dx + dy * dy + dz * dz);
            if (d < dmin) { dmin = d; pmin = p; }
            if (d <= RADIUS) mask |= 1ull << p;
        }
        mask |= 1ull << pmin;

        // local part of mixed (recompute d with identical expression)
        const float inv2r2 = 1.f / (2.f * RADIUS * RADIUS);
        int nl = 0; int lp[12]; float lw[12], ldst[12];
        float msum = 0.f;
        for (int p = 0; p < 64; p++) {
            if ((mask >> p) & 1ull) {
                float dx = ax - posS[p], dy = ay - posS[64 + p], dz = az - posS[128 + p];
                float d = sqrtf(dx * dx + dy * dy + dz * dz);
                float mix = Lrow[p] * expf(-(d * d) * inv2r2);
                if (nl < 12) { lp[nl] = p; lw[nl] = mix; ldst[nl] = d; nl++; }
                msum += mix;
            }
        }

        // top-6 of masked bridge logits (stable iterative strict-max)
        float bv[6]; int bi[6];
#pragma unroll
        for (int kq = 0; kq < 6; kq++) {
            float best = -3.4e38f; int bb = 0;
            for (int p = 0; p < 64; p++) {
                bool chd = false;
#pragma unroll
                for (int jq = 0; jq < 6; jq++)
                    if (jq < kq) chd |= (bi[jq] == p);
                if (chd) continue;
                float v = ((mask >> p) & 1ull) ? NEGINF : Lrow[64 + p];
                if (v > best) { best = v; bb = p; }
            }
            bv[kq] = best; bi[kq] = bb;
        }
        const float mb = bv[0];
        float sb[6]; float es = 0.f;
#pragma unroll
        for (int kq = 0; kq < 6; kq++) { sb[kq] = expf(bv[kq] - mb); es += sb[kq]; }
        const float invb = 1.f / es;
#pragma unroll
        for (int kq = 0; kq < 6; kq++) { sb[kq] = BRS * (sb[kq] * invb); msum += sb[kq]; }

        const float denom = fmaxf(msum, 1e-6f);

        // final sparse weights (dense in Lrow cols 0..63 for writeback)
        for (int p = 0; p < 64; p++) Lrow[p] = 0.f;
        float lmass = 0.f, bmass = 0.f, mdist = 0.f;
        int n = 0;
        for (int i = 0; i < nl; i++) {
            float wgt = lw[i] / denom;
            Lrow[lp[i]] = wgt;
            lmass += wgt;
            mdist = fmaf(wgt, ldst[i], mdist);
            plS[r * 12 + n] = lp[i]; wlS[r * 12 + n] = wgt; n++;
        }
#pragma unroll
        for (int kq = 0; kq < 6; kq++) {
            float wgt = sb[kq] / denom;
            int p = bi[kq];
            Lrow[p] = wgt;
            bmass += wgt;
            float dx = ax - posS[p], dy = ay - posS[64 + p], dz = az - posS[128 + p];
            float d = sqrtf(dx * dx + dy * dy + dz * dz);
            mdist = fmaf(wgt, d, mdist);
            plS[r * 12 + n] = p; wlS[r * 12 + n] = wgt; n++;
        }
        cntS[r] = n;

        // scalar outputs
        const size_t Bt = (size_t)Btot;
        float* o_ap = out + Bt * 256;
        o_ap[(size_t)row * 3 + 0] = ax;
        o_ap[(size_t)row * 3 + 1] = ay;
        o_ap[(size_t)row * 3 + 2] = az;
        out[Bt * 259 + row] = lmass;
        out[Bt * 260 + row] = bmass;
        out[Bt * 261 + row] = mdist;
        out[Bt * 262 + row] = RADIUS;
        out[Bt * 263 + row] = BRS;
    }
    __syncthreads();

    // ---- GEMM2: patch_state = sparse weights @ patch_values (pv via L1) ----
    const float4* pv4 = (const float4*)pvals;
    float4* out4 = (float4*)out;
    for (int c = tid; c < BM * 48; c += TPB) {
        const int r = c / 48, h4 = c - r * 48;
        const int n = cntS[r];
        float4 a4 = make_float4(0.f, 0.f, 0.f, 0.f);
        for (int i = 0; i < n; i++) {
            const float wgt = wlS[r * 12 + i];
            const int p = plS[r * 12 + i];
            const float4 v = __ldg(&pv4[p * 48 + h4]);
            a4.x = fmaf(wgt, v.x, a4.x);
            a4.y = fmaf(wgt, v.y, a4.y);
            a4.z = fmaf(wgt, v.z, a4.z);
            a4.w = fmaf(wgt, v.w, a4.w);
        }
        out4[(size_t)(r0 + r) * 48 + h4] = a4;
    }

    // ---- dense weights writeback ----
    float* outw = out + (size_t)Btot * Hdim;
    for (int i = tid; i < BM * 64; i += TPB) {
        const int r = i >> 6, p = i & 63;
        outw[(size_t)(r0 + r) * 64 + p] = Lsh[r * 130 + p];
    }
}

extern "C" void kernel_launch(void* const* d_in, const int* in_sizes, int n_in,
                              void* d_out, int out_size)
{
    const float* token = (const float*)d_in[0];
    const float* prev  = (const float*)d_in[1];
    const float* Wsel  = (const float*)d_in[2];
    const float* bsel  = (const float*)d_in[3];
    const float* Wbr   = (const float*)d_in[4];
    const float* bbr   = (const float*)d_in[5];
    const float* pvals = (const float*)d_in[6];
    const float* ppos  = (const float*)d_in[7];
    float* out = (float*)d_out;

    const int B = in_sizes[0] / Hdim;
    cudaFuncSetAttribute(taps_f32x2_kernel,
                         cudaFuncAttributeMaxDynamicSharedMemorySize, SMEM_BYTES);
    taps_f32x2_kernel<<<B / BM, TPB, SMEM_BYTES>>>(token, prev, Wsel, bsel, Wbr, bbr,
                                                   pvals, ppos, out, B);
}

// round 15
// speedup vs baseline: 1.7579x; 1.0001x over previous
#include <cuda_runtime.h>
#include <math.h>
#include <cstdint>

#define TPB    256
#define BM     128
#define BK     32
#define NCH    12
#define Hdim   192
#define K2H    384
#define RADIUS 0.42f
#define BRS    0.18f
#define NEGINF -1e9f

typedef unsigned long long ull;

// ---- smem (bytes) ----
// GEMM overlay: A [k][row] stride 138 floats, B [k][p] stride 132 floats
#define AS_STR  138
#define BS_STR  132
#define AS_BUF  (BK*AS_STR)      // 4416 floats
#define BS_BUF  (BK*BS_STR)      // 4224 floats
#define OFF_AS  0                // 2*4416*4 = 35328
#define OFF_BS  35328            // 2*4224*4 = 33792 -> 69120
// epilogue arena (all written AFTER GEMM completes; overlays AS/BS)
#define OFF_LSH  0               // 128*130*4 = 66560
#define OFF_CNT  66560           // 512 -> 67072
#define OFF_PL   67072           // 128*12*4 -> 73216
#define OFF_WL   73216           // 128*12*4 -> 79360
// live across whole kernel (beyond GEMM region end 69120)
#define OFF_POS  79360           // 192*4 -> 80128
#define OFF_BIAS 80128           // 128*4 -> 80640
#define SMEM_BYTES 80640

#define PACK2(dst, x, y) asm("mov.b64 %0, {%1, %2};" : "=l"(dst) : "r"(x), "r"(y))
#define FFMA2(acc, a, b) asm("fma.rn.f32x2 %0, %1, %2, %0;" : "+l"(acc) : "l"(a), "l"(b))
#define UNPK2(lo, hi, v) asm("mov.b64 {%0, %1}, %2;" : "=r"(lo), "=r"(hi) : "l"(v))

__global__ void __launch_bounds__(TPB, 2)
taps_f32x2_kernel(const float* __restrict__ token,
                  const float* __restrict__ prev,
                  const float* __restrict__ Wsel,
                  const float* __restrict__ bsel,
                  const float* __restrict__ Wbr,
                  const float* __restrict__ bbr,
                  const float* __restrict__ pvals,
                  const float* __restrict__ ppos,
                  float* __restrict__ out,
                  int Btot)
{
    extern __shared__ float sm[];
    float* As   = sm + (OFF_AS  >> 2);
    float* Bs   = sm + (OFF_BS  >> 2);
    float* Lsh  = sm + (OFF_LSH >> 2);
    int*   cntS = (int*)(sm + (OFF_CNT >> 2));
    int*   plS  = (int*)(sm + (OFF_PL  >> 2));
    float* wlS  = sm + (OFF_WL  >> 2);
    float* posS = sm + (OFF_POS >> 2);
    float* biasS= sm + (OFF_BIAS>> 2);

    const int tid  = threadIdx.x;
    const int lane = tid & 31;
    const int w    = tid >> 5;            // warp 0..7: cols [w*16, w*16+16)
    const int r0   = blockIdx.x * BM;

    for (int i = tid; i < 192; i += TPB) { int p = i / 3, c = i % 3; posS[c * 64 + p] = ppos[i]; }
    if (tid < 128) biasS[tid] = (tid < 64) ? bsel[tid] : bbr[tid - 64];

    // ---- staging geometry (fixed per thread) ----
    const int f4    = tid & 7;            // float4 index along k within chunk
    const int rbase = tid >> 3;           // 0..31
    int aoff[4];
    const float* wp[4];
#pragma unroll
    for (int i = 0; i < 4; i++) {
        const int row = i * 32 + rbase;   // A row / B patch row
        aoff[i] = (r0 + row) * Hdim + f4 * 4;
        wp[i] = ((row < 64) ? (Wsel + (size_t)row * K2H)
                            : (Wbr + (size_t)(row - 64) * K2H)) + f4 * 4;
    }

    // ---- compute geometry ----
    const int g0 = lane & 7;                       // row-pair base
    const int c0 = w * 16 + ((lane >> 3) << 2);    // 4 output cols

    ull acc[8][4];
#pragma unroll
    for (int j = 0; j < 8; j++)
#pragma unroll
        for (int q = 0; q < 4; q++) acc[j][q] = 0ull;

    float4 vA[4], vB[4];

    // prologue: load chunk 0, store into buf 0
#pragma unroll
    for (int i = 0; i < 4; i++) {
        vA[i] = *(const float4*)(token + aoff[i]);
        vB[i] = *(const float4*)(wp[i]);
    }
    {
        float* A = As; float* Bst = Bs;
#pragma unroll
        for (int i = 0; i < 4; i++) {
            const int row = i * 32 + rbase;
            A[(f4 * 4 + 0) * AS_STR + row] = vA[i].x;
            A[(f4 * 4 + 1) * AS_STR + row] = vA[i].y;
            A[(f4 * 4 + 2) * AS_STR + row] = vA[i].z;
            A[(f4 * 4 + 3) * AS_STR + row] = vA[i].w;
            Bst[(f4 * 4 + 0) * BS_STR + row] = vB[i].x;
            Bst[(f4 * 4 + 1) * BS_STR + row] = vB[i].y;
            Bst[(f4 * 4 + 2) * BS_STR + row] = vB[i].z;
            Bst[(f4 * 4 + 3) * BS_STR + row] = vB[i].w;
        }
    }

    // ---- GEMM1: 12 chunks of BK=32, double-buffered ----
    for (int ch = 0; ch < NCH; ch++) {
        __syncthreads();
        const bool more = (ch < NCH - 1);
        if (more) {
            const int gk = (ch + 1) * BK;
            const float* Asrc = (gk < Hdim) ? token : prev;
            const int acol = (gk < Hdim) ? gk : gk - Hdim;
#pragma unroll
            for (int i = 0; i < 4; i++) {
                vA[i] = *(const float4*)(Asrc + aoff[i] + acol);
                vB[i] = *(const float4*)(wp[i] + gk);
            }
        }

        const ull*   A64 = (const ull*)(As + (ch & 1) * AS_BUF);
        const float* Bb  = Bs + (ch & 1) * BS_BUF + c0;
#pragma unroll
        for (int k = 0; k < BK; k++) {
            const ull* Ak = A64 + k * (AS_STR / 2);
            float4 b4 = *(const float4*)(Bb + k * BS_STR);
            ull bb0, bb1, bb2, bb3;
            const uint32_t u0 = __float_as_uint(b4.x), u1 = __float_as_uint(b4.y);
            const uint32_t u2 = __float_as_uint(b4.z), u3 = __float_as_uint(b4.w);
            PACK2(bb0, u0, u0);
            PACK2(bb1, u1, u1);
            PACK2(bb2, u2, u2);
            PACK2(bb3, u3, u3);
#pragma unroll
            for (int j = 0; j < 8; j++) {
                const ull aa = Ak[g0 + 8 * j];   // rows {2(g0+8j), 2(g0+8j)+1}
                FFMA2(acc[j][0], aa, bb0);
                FFMA2(acc[j][1], aa, bb1);
                FFMA2(acc[j][2], aa, bb2);
                FFMA2(acc[j][3], aa, bb3);
            }
        }

        if (more) {
            float* A   = As + ((ch + 1) & 1) * AS_BUF;
            float* Bst = Bs + ((ch + 1) & 1) * BS_BUF;
#pragma unroll
            for (int i = 0; i < 4; i++) {
                const int row = i * 32 + rbase;
                A[(f4 * 4 + 0) * AS_STR + row] = vA[i].x;
                A[(f4 * 4 + 1) * AS_STR + row] = vA[i].y;
                A[(f4 * 4 + 2) * AS_STR + row] = vA[i].z;
                A[(f4 * 4 + 3) * AS_STR + row] = vA[i].w;
                Bst[(f4 * 4 + 0) * BS_STR + row] = vB[i].x;
                Bst[(f4 * 4 + 1) * BS_STR + row] = vB[i].y;
                Bst[(f4 * 4 + 2) * BS_STR + row] = vB[i].z;
                Bst[(f4 * 4 + 3) * BS_STR + row] = vB[i].w;
            }
        }
    }
    __syncthreads();   // GEMM bufs dead; epilogue arena live

    // ---- stage logits (+bias) into Lsh ----
    {
        float b[4];
#pragma unroll
        for (int q = 0; q < 4; q++) b[q] = biasS[c0 + q];
#pragma unroll
        for (int j = 0; j < 8; j++) {
            const int row0 = 2 * (g0 + 8 * j);
#pragma unroll
            for (int q = 0; q < 4; q++) {
                uint32_t lo, hi;
                UNPK2(lo, hi, acc[j][q]);
                Lsh[row0 * 130 + c0 + q]       = __uint_as_float(lo) + b[q];
                Lsh[(row0 + 1) * 130 + c0 + q] = __uint_as_float(hi) + b[q];
            }
        }
    }
    __syncthreads();

    // ---- per-row epilogue (round-2/12 validated semantics) ----
    if (tid < BM) {
        const int r = tid;
        const int row = r0 + r;
        float* Lrow = Lsh + r * 130;

        // softmax over sel logits
        float m = -3.4e38f;
        for (int p = 0; p < 64; p++) m = fmaxf(m, Lrow[p]);
        float s = 0.f;
        for (int p = 0; p < 64; p++) { float e = expf(Lrow[p] - m); Lrow[p] = e; s += e; }
        const float invs = 1.f / s;

        // base_weights + anchor position
        float ax = 0.f, ay = 0.f, az = 0.f;
        for (int p = 0; p < 64; p++) {
            float wgt = Lrow[p] * invs;
            Lrow[p] = wgt;
            ax = fmaf(wgt, posS[p], ax);
            ay = fmaf(wgt, posS[64 + p], ay);
            az = fmaf(wgt, posS[128 + p], az);
        }

        // distances + argmin (first occurrence) + local mask bits
        float dmin = 3.4e38f; int pmin = 0;
        unsigned long long mask = 0ull;
        for (int p = 0; p < 64; p++) {
            float dx = ax - posS[p], dy = ay - posS[64 + p], dz = az - posS[128 + p];
            float d = sqrtf(dx * dx + dy * dy + dz * dz);
            if (d < dmin) { dmin = d; pmin = p; }
            if (d <= RADIUS) mask |= 1ull << p;
        }
        mask |= 1ull << pmin;

        // local part of mixed (recompute d with identical expression)
        const float inv2r2 = 1.f / (2.f * RADIUS * RADIUS);
        int nl = 0; int lp[12]; float lw[12], ldst[12];
        float msum = 0.f;
        for (int p = 0; p < 64; p++) {
            if ((mask >> p) & 1ull) {
                float dx = ax - posS[p], dy = ay - posS[64 + p], dz = az - posS[128 + p];
                float d = sqrtf(dx * dx + dy * dy + dz * dz);
                float mix = Lrow[p] * expf(-(d * d) * inv2r2);
                if (nl < 12) { lp[nl] = p; lw[nl] = mix; ldst[nl] = d; nl++; }
                msum += mix;
            }
        }

        // top-6 of masked bridge logits (stable iterative strict-max)
        float bv[6]; int bi[6];
#pragma unroll
        for (int kq = 0; kq < 6; kq++) {
            float best = -3.4e38f; int bb = 0;
            for (int p = 0; p < 64; p++) {
                bool chd = false;
#pragma unroll
                for (int jq = 0; jq < 6; jq++)
                    if (jq < kq) chd |= (bi[jq] == p);
                if (chd) continue;
                float v = ((mask >> p) & 1ull) ? NEGINF : Lrow[64 + p];
                if (v > best) { best = v; bb = p; }
            }
            bv[kq] = best; bi[kq] = bb;
        }
        const float mb = bv[0];
        float sb[6]; float es = 0.f;
#pragma unroll
        for (int kq = 0; kq < 6; kq++) { sb[kq] = expf(bv[kq] - mb); es += sb[kq]; }
        const float invb = 1.f / es;
#pragma unroll
        for (int kq = 0; kq < 6; kq++) { sb[kq] = BRS * (sb[kq] * invb); msum += sb[kq]; }

        const float denom = fmaxf(msum, 1e-6f);

        // final sparse weights (dense in Lrow cols 0..63 for writeback)
        for (int p = 0; p < 64; p++) Lrow[p] = 0.f;
        float lmass = 0.f, bmass = 0.f, mdist = 0.f;
        int n = 0;
        for (int i = 0; i < nl; i++) {
            float wgt = lw[i] / denom;
            Lrow[lp[i]] = wgt;
            lmass += wgt;
            mdist = fmaf(wgt, ldst[i], mdist);
            plS[r * 12 + n] = lp[i]; wlS[r * 12 + n] = wgt; n++;
        }
#pragma unroll
        for (int kq = 0; kq < 6; kq++) {
            float wgt = sb[kq] / denom;
            int p = bi[kq];
            Lrow[p] = wgt;
            bmass += wgt;
            float dx = ax - posS[p], dy = ay - posS[64 + p], dz = az - posS[128 + p];
            float d = sqrtf(dx * dx + dy * dy + dz * dz);
            mdist = fmaf(wgt, d, mdist);
            plS[r * 12 + n] = p; wlS[r * 12 + n] = wgt; n++;
        }
        cntS[r] = n;

        // scalar outputs
        const size_t Bt = (size_t)Btot;
        float* o_ap = out + Bt * 256;
        o_ap[(size_t)row * 3 + 0] = ax;
        o_ap[(size_t)row * 3 + 1] = ay;
        o_ap[(size_t)row * 3 + 2] = az;
        out[Bt * 259 + row] = lmass;
        out[Bt * 260 + row] = bmass;
        out[Bt * 261 + row] = mdist;
        out[Bt * 262 + row] = RADIUS;
        out[Bt * 263 + row] = BRS;
    }
    __syncthreads();

    // ---- GEMM2: patch_state = sparse weights @ patch_values (pv via L1) ----
    const float4* pv4 = (const float4*)pvals;
    float4* out4 = (float4*)out;
    for (int c = tid; c < BM * 48; c += TPB) {
        const int r = c / 48, h4 = c - r * 48;
        const int n = cntS[r];
        float4 a4 = make_float4(0.f, 0.f, 0.f, 0.f);
        for (int i = 0; i < n; i++) {
            const float wgt = wlS[r * 12 + i];
            const int p = plS[r * 12 + i];
            const float4 v = __ldg(&pv4[p * 48 + h4]);
            a4.x = fmaf(wgt, v.x, a4.x);
            a4.y = fmaf(wgt, v.y, a4.y);
            a4.z = fmaf(wgt, v.z, a4.z);
            a4.w = fmaf(wgt, v.w, a4.w);
        }
        out4[(size_t)(r0 + r) * 48 + h4] = a4;
    }

    // ---- dense weights writeback ----
    float* outw = out + (size_t)Btot * Hdim;
    for (int i = tid; i < BM * 64; i += TPB) {
        const int r = i >> 6, p = i & 63;
        outw[(size_t)(r0 + r) * 64 + p] = Lsh[r * 130 + p];
    }
}

extern "C" void kernel_launch(void* const* d_in, const int* in_sizes, int n_in,
                              void* d_out, int out_size)
{
    const float* token = (const float*)d_in[0];
    const float* prev  = (const float*)d_in[1];
    const float* Wsel  = (const float*)d_in[2];
    const float* bsel  = (const float*)d_in[3];
    const float* Wbr   = (const float*)d_in[4];
    const float* bbr   = (const float*)d_in[5];
    const float* pvals = (const float*)d_in[6];
    const float* ppos  = (const float*)d_in[7];
    float* out = (float*)d_out;

    const int B = in_sizes[0] / Hdim;
    cudaFuncSetAttribute(taps_f32x2_kernel,
                         cudaFuncAttributeMaxDynamicSharedMemorySize, SMEM_BYTES);
    taps_f32x2_kernel<<<B / BM, TPB, SMEM_BYTES>>>(token, prev, Wsel, bsel, Wbr, bbr,
                                                   pvals, ppos, out, B);
}

// round 17
// speedup vs baseline: 1.7586x; 1.0004x over previous
#include <cuda_runtime.h>
#include <math.h>
#include <cstdint>

#define TPB    256
#define BM     128
#define BK     32
#define NCH    12
#define Hdim   192
#define K2H    384
#define RADIUS 0.42f
#define BRS    0.18f
#define NEGINF -1e9f

typedef unsigned long long ull;

// ---- smem (bytes) ----
// GEMM overlay: A [k][row] stride 138 floats, B [k][p] stride 132 floats
#define AS_STR  138
#define BS_STR  132
#define AS_BUF  (BK*AS_STR)      // 4416 floats
#define BS_BUF  (BK*BS_STR)      // 4224 floats
#define OFF_AS  0                // 2*4416*4 = 35328
#define OFF_BS  35328            // 2*4224*4 = 33792 -> 69120
// epilogue arena (all written AFTER GEMM completes; overlays AS/BS)
#define OFF_LSH  0               // 128*130*4 = 66560
#define OFF_CNT  66560           // 512 -> 67072
#define OFF_PL   67072           // 128*12*4 -> 73216
#define OFF_WL   73216           // 128*12*4 -> 79360
// live across whole kernel (beyond GEMM region end 69120)
#define OFF_POS  79360           // 192*4 -> 80128
#define OFF_BIAS 80128           // 128*4 -> 80640
#define SMEM_BYTES 80640

#define PACK2(dst, x, y) asm("mov.b64 %0, {%1, %2};" : "=l"(dst) : "r"(x), "r"(y))
#define FFMA2(acc, a, b) asm("fma.rn.f32x2 %0, %1, %2, %0;" : "+l"(acc) : "l"(a), "l"(b))
#define UNPK2(lo, hi, v) asm("mov.b64 {%0, %1}, %2;" : "=r"(lo), "=r"(hi) : "l"(v))

__global__ void __launch_bounds__(TPB, 2)
taps_f32x2_kernel(const float* __restrict__ token,
                  const float* __restrict__ prev,
                  const float* __restrict__ Wsel,
                  const float* __restrict__ bsel,
                  const float* __restrict__ Wbr,
                  const float* __restrict__ bbr,
                  const float* __restrict__ pvals,
                  const float* __restrict__ ppos,
                  float* __restrict__ out,
                  int Btot)
{
    extern __shared__ float sm[];
    float* As   = sm + (OFF_AS  >> 2);
    float* Bs   = sm + (OFF_BS  >> 2);
    float* Lsh  = sm + (OFF_LSH >> 2);
    int*   cntS = (int*)(sm + (OFF_CNT >> 2));
    int*   plS  = (int*)(sm + (OFF_PL  >> 2));
    float* wlS  = sm + (OFF_WL  >> 2);
    float* posS = sm + (OFF_POS >> 2);
    float* biasS= sm + (OFF_BIAS>> 2);

    const int tid  = threadIdx.x;
    const int lane = tid & 31;
    const int w    = tid >> 5;            // warp 0..7: cols [w*16, w*16+16)
    const int r0   = blockIdx.x * BM;

    for (int i = tid; i < 192; i += TPB) { int p = i / 3, c = i % 3; posS[c * 64 + p] = ppos[i]; }
    if (tid < 128) biasS[tid] = (tid < 64) ? bsel[tid] : bbr[tid - 64];

    // ---- staging geometry (fixed per thread) ----
    const int f4    = tid & 7;            // float4 index along k within chunk
    const int rbase = tid >> 3;           // 0..31
    int aoff[4];
    const float* wp[4];
#pragma unroll
    for (int i = 0; i < 4; i++) {
        const int row = i * 32 + rbase;   // A row / B patch row
        aoff[i] = (r0 + row) * Hdim + f4 * 4;
        wp[i] = ((row < 64) ? (Wsel + (size_t)row * K2H)
                            : (Wbr + (size_t)(row - 64) * K2H)) + f4 * 4;
    }

    // ---- compute geometry ----
    const int g0 = lane & 7;                       // row-pair base
    const int c0 = w * 16 + ((lane >> 3) << 2);    // 4 output cols

    ull acc[8][4];
#pragma unroll
    for (int j = 0; j < 8; j++)
#pragma unroll
        for (int q = 0; q < 4; q++) acc[j][q] = 0ull;

    float4 vA[4], vB[4];

    // prologue: load chunk 0, store into buf 0
#pragma unroll
    for (int i = 0; i < 4; i++) {
        vA[i] = *(const float4*)(token + aoff[i]);
        vB[i] = *(const float4*)(wp[i]);
    }
    {
        float* A = As; float* Bst = Bs;
#pragma unroll
        for (int i = 0; i < 4; i++) {
            const int row = i * 32 + rbase;
            A[(f4 * 4 + 0) * AS_STR + row] = vA[i].x;
            A[(f4 * 4 + 1) * AS_STR + row] = vA[i].y;
            A[(f4 * 4 + 2) * AS_STR + row] = vA[i].z;
            A[(f4 * 4 + 3) * AS_STR + row] = vA[i].w;
            Bst[(f4 * 4 + 0) * BS_STR + row] = vB[i].x;
            Bst[(f4 * 4 + 1) * BS_STR + row] = vB[i].y;
            Bst[(f4 * 4 + 2) * BS_STR + row] = vB[i].z;
            Bst[(f4 * 4 + 3) * BS_STR + row] = vB[i].w;
        }
    }

    // ---- GEMM1: 12 chunks of BK=32, double-buffered ----
    for (int ch = 0; ch < NCH; ch++) {
        __syncthreads();
        const bool more = (ch < NCH - 1);
        if (more) {
            const int gk = (ch + 1) * BK;
            const float* Asrc = (gk < Hdim) ? token : prev;
            const int acol = (gk < Hdim) ? gk : gk - Hdim;
#pragma unroll
            for (int i = 0; i < 4; i++) {
                vA[i] = *(const float4*)(Asrc + aoff[i] + acol);
                vB[i] = *(const float4*)(wp[i] + gk);
            }
        }

        const ull*   A64 = (const ull*)(As + (ch & 1) * AS_BUF);
        const float* Bb  = Bs + (ch & 1) * BS_BUF + c0;
#pragma unroll
        for (int k = 0; k < BK; k++) {
            const ull* Ak = A64 + k * (AS_STR / 2);
            float4 b4 = *(const float4*)(Bb + k * BS_STR);
            ull bb0, bb1, bb2, bb3;
            const uint32_t u0 = __float_as_uint(b4.x), u1 = __float_as_uint(b4.y);
            const uint32_t u2 = __float_as_uint(b4.z), u3 = __float_as_uint(b4.w);
            PACK2(bb0, u0, u0);
            PACK2(bb1, u1, u1);
            PACK2(bb2, u2, u2);
            PACK2(bb3, u3, u3);
#pragma unroll
            for (int j = 0; j < 8; j++) {
                const ull aa = Ak[g0 + 8 * j];   // rows {2(g0+8j), 2(g0+8j)+1}
                FFMA2(acc[j][0], aa, bb0);
                FFMA2(acc[j][1], aa, bb1);
                FFMA2(acc[j][2], aa, bb2);
                FFMA2(acc[j][3], aa, bb3);
            }
        }

        if (more) {
            float* A   = As + ((ch + 1) & 1) * AS_BUF;
            float* Bst = Bs + ((ch + 1) & 1) * BS_BUF;
#pragma unroll
            for (int i = 0; i < 4; i++) {
                const int row = i * 32 + rbase;
                A[(f4 * 4 + 0) * AS_STR + row] = vA[i].x;
                A[(f4 * 4 + 1) * AS_STR + row] = vA[i].y;
                A[(f4 * 4 + 2) * AS_STR + row] = vA[i].z;
                A[(f4 * 4 + 3) * AS_STR + row] = vA[i].w;
                Bst[(f4 * 4 + 0) * BS_STR + row] = vB[i].x;
                Bst[(f4 * 4 + 1) * BS_STR + row] = vB[i].y;
                Bst[(f4 * 4 + 2) * BS_STR + row] = vB[i].z;
                Bst[(f4 * 4 + 3) * BS_STR + row] = vB[i].w;
            }
        }
    }
    __syncthreads();   // GEMM bufs dead; epilogue arena live

    // ---- stage logits (+bias) into Lsh ----
    {
        float b[4];
#pragma unroll
        for (int q = 0; q < 4; q++) b[q] = biasS[c0 + q];
#pragma unroll
        for (int j = 0; j < 8; j++) {
            const int row0 = 2 * (g0 + 8 * j);
#pragma unroll
            for (int q = 0; q < 4; q++) {
                uint32_t lo, hi;
                UNPK2(lo, hi, acc[j][q]);
                Lsh[row0 * 130 + c0 + q]       = __uint_as_float(lo) + b[q];
                Lsh[(row0 + 1) * 130 + c0 + q] = __uint_as_float(hi) + b[q];
            }
        }
    }
    __syncthreads();

    // ---- per-row epilogue (round-2/12 validated semantics) ----
    if (tid < BM) {
        const int r = tid;
        const int row = r0 + r;
        float* Lrow = Lsh + r * 130;

        // softmax over sel logits
        float m = -3.4e38f;
        for (int p = 0; p < 64; p++) m = fmaxf(m, Lrow[p]);
        float s = 0.f;
        for (int p = 0; p < 64; p++) { float e = expf(Lrow[p] - m); Lrow[p] = e; s += e; }
        const float invs = 1.f / s;

        // base_weights + anchor position
        float ax = 0.f, ay = 0.f, az = 0.f;
        for (int p = 0; p < 64; p++) {
            float wgt = Lrow[p] * invs;
            Lrow[p] = wgt;
            ax = fmaf(wgt, posS[p], ax);
            ay = fmaf(wgt, posS[64 + p], ay);
            az = fmaf(wgt, posS[128 + p], az);
        }

        // distances + argmin (first occurrence) + local mask bits
        float dmin = 3.4e38f; int pmin = 0;
        unsigned long long mask = 0ull;
        for (int p = 0; p < 64; p++) {
            float dx = ax - posS[p], dy = ay - posS[64 + p], dz = az - posS[128 + p];
            float d = sqrtf(dx * dx + dy * dy + dz * dz);
            if (d < dmin) { dmin = d; pmin = p; }
            if (d <= RADIUS) mask |= 1ull << p;
        }
        mask |= 1ull << pmin;

        // local part of mixed (recompute d with identical expression)
        const float inv2r2 = 1.f / (2.f * RADIUS * RADIUS);
        int nl = 0; int lp[12]; float lw[12], ldst[12];
        float msum = 0.f;
        for (int p = 0; p < 64; p++) {
            if ((mask >> p) & 1ull) {
                float dx = ax - posS[p], dy = ay - posS[64 + p], dz = az - posS[128 + p];
                float d = sqrtf(dx * dx + dy * dy + dz * dz);
                float mix = Lrow[p] * expf(-(d * d) * inv2r2);
                if (nl < 12) { lp[nl] = p; lw[nl] = mix; ldst[nl] = d; nl++; }
                msum += mix;
            }
        }

        // top-6 of masked bridge logits (stable iterative strict-max)
        float bv[6]; int bi[6];
#pragma unroll
        for (int kq = 0; kq < 6; kq++) {
            float best = -3.4e38f; int bb = 0;
            for (int p = 0; p < 64; p++) {
                bool chd = false;
#pragma unroll
                for (int jq = 0; jq < 6; jq++)
                    if (jq < kq) chd |= (bi[jq] == p);
                if (chd) continue;
                float v = ((mask >> p) & 1ull) ? NEGINF : Lrow[64 + p];
                if (v > best) { best = v; bb = p; }
            }
            bv[kq] = best; bi[kq] = bb;
        }
        const float mb = bv[0];
        float sb[6]; float es = 0.f;
#pragma unroll
        for (int kq = 0; kq < 6; kq++) { sb[kq] = expf(bv[kq] - mb); es += sb[kq]; }
        const float invb = 1.f / es;
#pragma unroll
        for (int kq = 0; kq < 6; kq++) { sb[kq] = BRS * (sb[kq] * invb); msum += sb[kq]; }

        const float denom = fmaxf(msum, 1e-6f);

        // final sparse weights (dense in Lrow cols 0..63 for writeback)
        for (int p = 0; p < 64; p++) Lrow[p] = 0.f;
        float lmass = 0.f, bmass = 0.f, mdist = 0.f;
        int n = 0;
        for (int i = 0; i < nl; i++) {
            float wgt = lw[i] / denom;
            Lrow[lp[i]] = wgt;
            lmass += wgt;
            mdist = fmaf(wgt, ldst[i], mdist);
            plS[r * 12 + n] = lp[i]; wlS[r * 12 + n] = wgt; n++;
        }
#pragma unroll
        for (int kq = 0; kq < 6; kq++) {
            float wgt = sb[kq] / denom;
            int p = bi[kq];
            Lrow[p] = wgt;
            bmass += wgt;
            float dx = ax - posS[p], dy = ay - posS[64 + p], dz = az - posS[128 + p];
            float d = sqrtf(dx * dx + dy * dy + dz * dz);
            mdist = fmaf(wgt, d, mdist);
            plS[r * 12 + n] = p; wlS[r * 12 + n] = wgt; n++;
        }
        cntS[r] = n;

        // scalar outputs
        const size_t Bt = (size_t)Btot;
        float* o_ap = out + Bt * 256;
        o_ap[(size_t)row * 3 + 0] = ax;
        o_ap[(size_t)row * 3 + 1] = ay;
        o_ap[(size_t)row * 3 + 2] = az;
        out[Bt * 259 + row] = lmass;
        out[Bt * 260 + row] = bmass;
        out[Bt * 261 + row] = mdist;
        out[Bt * 262 + row] = RADIUS;
        out[Bt * 263 + row] = BRS;
    }
    __syncthreads();

    // ---- GEMM2: patch_state = sparse weights @ patch_values (pv via L1) ----
    const float4* pv4 = (const float4*)pvals;
    float4* out4 = (float4*)out;
    for (int c = tid; c < BM * 48; c += TPB) {
        const int r = c / 48, h4 = c - r * 48;
        const int n = cntS[r];
        float4 a4 = make_float4(0.f, 0.f, 0.f, 0.f);
        for (int i = 0; i < n; i++) {
            const float wgt = wlS[r * 12 + i];
            const int p = plS[r * 12 + i];
            const float4 v = __ldg(&pv4[p * 48 + h4]);
            a4.x = fmaf(wgt, v.x, a4.x);
            a4.y = fmaf(wgt, v.y, a4.y);
            a4.z = fmaf(wgt, v.z, a4.z);
            a4.w = fmaf(wgt, v.w, a4.w);
        }
        out4[(size_t)(r0 + r) * 48 + h4] = a4;
    }

    // ---- dense weights writeback ----
    float* outw = out + (size_t)Btot * Hdim;
    for (int i = tid; i < BM * 64; i += TPB) {
        const int r = i >> 6, p = i & 63;
        outw[(size_t)(r0 + r) * 64 + p] = Lsh[r * 130 + p];
    }
}

extern "C" void kernel_launch(void* const* d_in, const int* in_sizes, int n_in,
                              void* d_out, int out_size)
{
    const float* token = (const float*)d_in[0];
    const float* prev  = (const float*)d_in[1];
    const float* Wsel  = (const float*)d_in[2];
    const float* bsel  = (const float*)d_in[3];
    const float* Wbr   = (const float*)d_in[4];
    const float* bbr   = (const float*)d_in[5];
    const float* pvals = (const float*)d_in[6];
    const float* ppos  = (const float*)d_in[7];
    float* out = (float*)d_out;

    const int B = in_sizes[0] / Hdim;
    cudaFuncSetAttribute(taps_f32x2_kernel,
                         cudaFuncAttributeMaxDynamicSharedMemorySize, SMEM_BYTES);
    taps_f32x2_kernel<<<B / BM, TPB, SMEM_BYTES>>>(token, prev, Wsel, bsel, Wbr, bbr,
                                                   pvals, ppos, out, B);
}